// round 4
// baseline (speedup 1.0000x reference)
#include <cuda_runtime.h>
#include <cstdint>

// ============================================================================
// MultiHeadAttentionQuantum — algebraic collapse:
//   out[t,e] = b[e] + sum_{h,i} W[e,4h+i] * ( m01_h(t)^T R[h][i] m23_h(t) )
// where m01/m23 are 9-vectors of monomials in (1, cos x, sin x) of the 4
// angles of head h, and R is an 8x4x9x9 coefficient tensor computed once per
// launch from params (prologue kernel).
// Main kernel: packed f32x2 (2 tokens/thread) via PTX fma.rn.f32x2.
// ============================================================================

#define NQ      4
#define LAYERS  2
#define HEADS   8
#define EMBED   32
#define TOKENS  (32 * 4096)          // B*S = 131072
#define HALF_T  (TOKENS / 2)         // 65536 threads

// R coefficients: [h][i][a][b], a,b in 0..8
__device__ float g_R[HEADS * 4 * 9 * 9];

// ---------------------------------------------------------------------------
// f32x2 packed helpers
// ---------------------------------------------------------------------------
typedef unsigned long long u64;

__device__ __forceinline__ u64 pack2(float a, float b) {
    u64 r; asm("mov.b64 %0, {%1, %2};" : "=l"(r) : "f"(a), "f"(b)); return r;
}
__device__ __forceinline__ void unpack2(u64 a, float& x, float& y) {
    asm("mov.b64 {%0, %1}, %2;" : "=f"(x), "=f"(y) : "l"(a));
}
__device__ __forceinline__ u64 fma2(u64 a, u64 b, u64 c) {
    u64 d; asm("fma.rn.f32x2 %0, %1, %2, %3;" : "=l"(d) : "l"(a), "l"(b), "l"(c)); return d;
}
__device__ __forceinline__ u64 mul2(u64 a, u64 b) {
    u64 d; asm("mul.rn.f32x2 %0, %1, %2;" : "=l"(d) : "l"(a), "l"(b)); return d;
}

// ---------------------------------------------------------------------------
// Prologue: build U_h (16x16 complex) from params, then A = Re(U^H D_i U),
// then R[h][i] in the (1,cos,sin) monomial basis.  Grid: 32 blocks (h,i).
// ---------------------------------------------------------------------------
__device__ __forceinline__ float vfac(int t, int j, int k) {
    // w(j,k) over basis [1, cos x, sin x]:
    // w(0,0) = .5 + .5 cos ; w(1,1) = .5 - .5 cos ; w(0,1)=w(1,0) = .5 sin
    if (t == 0) return (j == k) ? 0.5f : 0.0f;
    if (t == 1) return (j == k) ? (j ? -0.5f : 0.5f) : 0.0f;
    return (j != k) ? 0.5f : 0.0f;
}

__global__ void build_coeffs_kernel(const float* __restrict__ params) {
    __shared__ float Ur[16][16], Ui[16][16];
    __shared__ float A[16][16];

    const int h   = blockIdx.x >> 2;
    const int obs = blockIdx.x & 3;
    const int tid = threadIdx.x;

    // identity
    {
        int r = tid >> 4, c = tid & 15;
        Ur[r][c] = (r == c) ? 1.0f : 0.0f;
        Ui[r][c] = 0.0f;
    }
    __syncthreads();

    for (int l = 0; l < LAYERS; l++) {
        for (int q = 0; q < NQ; q++) {
            const float* p = params + ((h * LAYERS + l) * NQ + q) * 3;
            float t0 = p[0], t1 = p[1], t2 = p[2];
            float c0 = cosf(0.5f * t0), s0 = sinf(0.5f * t0);
            float c1 = cosf(0.5f * t1), s1 = sinf(0.5f * t1);
            float cz = cosf(0.5f * t2), sz = sinf(0.5f * t2);
            // M = Ry(t1) * Rx(t0)
            float M00r =  c1 * c0, M00i =  s1 * s0;
            float M01r = -s1 * c0, M01i = -c1 * s0;
            float M10r =  s1 * c0, M10i = -c1 * s0;
            float M11r =  c1 * c0, M11i = -s1 * s0;
            // G = Rz(t2) * M : row0 *= (cz - i sz), row1 *= (cz + i sz)
            float G00r = M00r * cz + M00i * sz, G00i = M00i * cz - M00r * sz;
            float G01r = M01r * cz + M01i * sz, G01i = M01i * cz - M01r * sz;
            float G10r = M10r * cz - M10i * sz, G10i = M10i * cz + M10r * sz;
            float G11r = M11r * cz - M11i * sz, G11i = M11i * cz + M11r * sz;

            if (tid < 128) {
                int pr = tid >> 4, col = tid & 15;
                int bp = 3 - q, msk = 1 << bp;
                int low = pr & (msk - 1);
                int r0 = ((pr >> bp) << (bp + 1)) | low;
                int r1 = r0 | msk;
                float ar = Ur[r0][col], ai = Ui[r0][col];
                float br = Ur[r1][col], bi = Ui[r1][col];
                Ur[r0][col] = G00r * ar - G00i * ai + G01r * br - G01i * bi;
                Ui[r0][col] = G00r * ai + G00i * ar + G01r * bi + G01i * br;
                Ur[r1][col] = G10r * ar - G10i * ai + G11r * br - G11i * bi;
                Ui[r1][col] = G10r * ai + G10i * ar + G11r * bi + G11i * br;
            }
            __syncthreads();
        }
        // CNOT chain (0,1),(1,2),(2,3),(3,0): (C@U)[r] = U[sigma(r)]
        for (int e = 0; e < 4; e++) {
            int cw = e, tw = (e + 1) & 3;
            int cm = 1 << (3 - cw), tm = 1 << (3 - tw);
            int r = tid >> 4, col = tid & 15;
            int src = (r & cm) ? (r ^ tm) : r;
            float vr = Ur[src][col], vi = Ui[src][col];
            __syncthreads();
            Ur[r][col] = vr; Ui[r][col] = vi;
            __syncthreads();
        }
    }

    // A[j][k] = sum_r D_obs[r] * (Ur[r][j]Ur[r][k] + Ui[r][j]Ui[r][k])
    {
        int j = tid >> 4, k = tid & 15;
        int bp = 3 - obs;
        float s = 0.0f;
        #pragma unroll
        for (int r = 0; r < 16; r++) {
            float sign = ((r >> bp) & 1) ? -1.0f : 1.0f;
            s += sign * (Ur[r][j] * Ur[r][k] + Ui[r][j] * Ui[r][k]);
        }
        A[j][k] = s;
    }
    __syncthreads();

    // R[a][b] = sum_{j,k} A[j][k] * prod_q V[tq](jq,kq)
    if (tid < 81) {
        int t0 = tid / 27, t1 = (tid / 9) % 3, t2 = (tid / 3) % 3, t3 = tid % 3;
        float s = 0.0f;
        for (int j = 0; j < 16; j++)
            for (int k = 0; k < 16; k++) {
                float f = vfac(t0, (j >> 3) & 1, (k >> 3) & 1)
                        * vfac(t1, (j >> 2) & 1, (k >> 2) & 1)
                        * vfac(t2, (j >> 1) & 1, (k >> 1) & 1)
                        * vfac(t3,  j       & 1,  k       & 1);
                if (f != 0.0f) s += f * A[j][k];
            }
        g_R[((h * 4 + obs) * 9 + (t0 * 3 + t1)) * 9 + (t2 * 3 + t3)] = s;
    }
}

// ---------------------------------------------------------------------------
// Main kernel: 2 tokens per thread (f32x2), coefficients duplicated in SMEM so
// LDS.128 yields packed operands directly.
// ---------------------------------------------------------------------------
__global__ void __launch_bounds__(256)
quantum_mha_kernel(const float* __restrict__ x,
                   const float* __restrict__ W,     // [32][32]
                   const float* __restrict__ bias,  // [32]
                   float* __restrict__ out) {
    // sR: [h][i][a][20]  (9 coeffs duplicated -> 18 floats, pad to 20)
    __shared__ __align__(16) float sR[HEADS * 4 * 9 * 20];   // 23040 B
    __shared__ __align__(16) float sW[EMBED * 64];           // W duplicated
    __shared__ __align__(16) float sb[64];                   // bias duplicated

    const int tid = threadIdx.x;
    for (int idx = tid; idx < HEADS * 4 * 9 * 9; idx += 256) {
        int b   = idx % 9;
        int hia = idx / 9;
        float v = g_R[idx];
        sR[hia * 20 + 2 * b]     = v;
        sR[hia * 20 + 2 * b + 1] = v;
    }
    for (int idx = tid; idx < EMBED * 32; idx += 256) {
        int e = idx >> 5, k = idx & 31;
        float v = W[e * 32 + k];
        sW[e * 64 + 2 * k]     = v;
        sW[e * 64 + 2 * k + 1] = v;
    }
    if (tid < 32) { float v = bias[tid]; sb[2 * tid] = v; sb[2 * tid + 1] = v; }
    __syncthreads();

    const int gid = blockIdx.x * 256 + tid;       // 0..65535
    const int tA = gid;
    const int tB = gid + HALF_T;

    const float4* xA4 = reinterpret_cast<const float4*>(x + (size_t)tA * 32);
    const float4* xB4 = reinterpret_cast<const float4*>(x + (size_t)tB * 32);

    u64 oacc[EMBED];
    #pragma unroll
    for (int e = 0; e < EMBED; e++)
        oacc[e] = *reinterpret_cast<const u64*>(&sb[2 * e]);

    #pragma unroll 1
    for (int h = 0; h < HEADS; h++) {
        float4 aA = xA4[h];
        float4 aB = xB4[h];

        float cA0, sA0, cA1, sA1, cA2, sA2, cA3, sA3;
        float cB0, sB0, cB1, sB1, cB2, sB2, cB3, sB3;
        __sincosf(aA.x, &sA0, &cA0);  __sincosf(aA.y, &sA1, &cA1);
        __sincosf(aA.z, &sA2, &cA2);  __sincosf(aA.w, &sA3, &cA3);
        __sincosf(aB.x, &sB0, &cB0);  __sincosf(aB.y, &sB1, &cB1);
        __sincosf(aB.z, &sB2, &cB2);  __sincosf(aB.w, &sB3, &cB3);

        u64 C0 = pack2(cA0, cB0), S0 = pack2(sA0, sB0);
        u64 C1 = pack2(cA1, cB1), S1 = pack2(sA1, sB1);
        u64 C2 = pack2(cA2, cB2), S2 = pack2(sA2, sB2);
        u64 C3 = pack2(cA3, cB3), S3 = pack2(sA3, sB3);

        // monomials over qubit pairs; index 0 (==1) handled structurally
        u64 m01[9], m23[9];
        m01[1] = C1; m01[2] = S1; m01[3] = C0;
        m01[4] = mul2(C0, C1); m01[5] = mul2(C0, S1);
        m01[6] = S0; m01[7] = mul2(S0, C1); m01[8] = mul2(S0, S1);
        m23[1] = C3; m23[2] = S3; m23[3] = C2;
        m23[4] = mul2(C2, C3); m23[5] = mul2(C2, S3);
        m23[6] = S2; m23[7] = mul2(S2, C3); m23[8] = mul2(S2, S3);

        const float* base = sR + h * (4 * 9 * 20);
        u64 ev[4];
        #pragma unroll
        for (int i = 0; i < 4; i++) {
            const float* rb = base + i * (9 * 20);
            u64 acc = 0;
            #pragma unroll
            for (int a = 0; a < 9; a++) {
                const ulonglong2* r2 = reinterpret_cast<const ulonglong2*>(rb + a * 20);
                ulonglong2 q0 = r2[0], q1 = r2[1], q2 = r2[2], q3 = r2[3];
                u64 q8 = *reinterpret_cast<const u64*>(rb + a * 20 + 16);
                u64 t = q0.x;                    // b = 0 term (m23[0] == 1)
                t = fma2(m23[1], q0.y, t);
                t = fma2(m23[2], q1.x, t);
                t = fma2(m23[3], q1.y, t);
                t = fma2(m23[4], q2.x, t);
                t = fma2(m23[5], q2.y, t);
                t = fma2(m23[6], q3.x, t);
                t = fma2(m23[7], q3.y, t);
                t = fma2(m23[8], q8,   t);
                acc = (a == 0) ? t : fma2(m01[a], t, acc);   // m01[0] == 1
            }
            ev[i] = acc;
        }

        // fold into outputs: oacc[e] += sum_i W[e][4h+i] * ev[i]
        #pragma unroll
        for (int e = 0; e < EMBED; e++) {
            const ulonglong2* w2 =
                reinterpret_cast<const ulonglong2*>(sW + e * 64 + h * 8);
            ulonglong2 wa = w2[0], wb = w2[1];
            u64 acc = oacc[e];
            acc = fma2(ev[0], wa.x, acc);
            acc = fma2(ev[1], wa.y, acc);
            acc = fma2(ev[2], wb.x, acc);
            acc = fma2(ev[3], wb.y, acc);
            oacc[e] = acc;
        }
    }

    float4* oA4 = reinterpret_cast<float4*>(out + (size_t)tA * 32);
    float4* oB4 = reinterpret_cast<float4*>(out + (size_t)tB * 32);
    #pragma unroll
    for (int g = 0; g < 8; g++) {
        float4 va, vb;
        unpack2(oacc[4 * g + 0], va.x, vb.x);
        unpack2(oacc[4 * g + 1], va.y, vb.y);
        unpack2(oacc[4 * g + 2], va.z, vb.z);
        unpack2(oacc[4 * g + 3], va.w, vb.w);
        oA4[g] = va;
        oB4[g] = vb;
    }
}

// ---------------------------------------------------------------------------
extern "C" void kernel_launch(void* const* d_in, const int* in_sizes, int n_in,
                              void* d_out, int out_size) {
    const float* x = nullptr;
    const float* params = nullptr;
    const float* W = nullptr;
    const float* bias = nullptr;
    for (int i = 0; i < n_in; i++) {
        int s = in_sizes[i];
        if      (s == TOKENS * EMBED)            x      = (const float*)d_in[i];
        else if (s == HEADS * LAYERS * NQ * 3)   params = (const float*)d_in[i];
        else if (s == EMBED * EMBED)             W      = (const float*)d_in[i];
        else if (s == EMBED)                     bias   = (const float*)d_in[i];
    }
    float* out = (float*)d_out;

    build_coeffs_kernel<<<HEADS * 4, 256>>>(params);
    quantum_mha_kernel<<<HALF_T / 256, 256>>>(x, W, bias, out);
}

// round 6
// speedup vs baseline: 1.1745x; 1.1745x over previous
#include <cuda_runtime.h>
#include <cstdint>

// ============================================================================
// MultiHeadAttentionQuantum — algebraic collapse:
//   out[t,e] = b[e] + sum_{h,i} W[e,4h+i] * ( m01_h(t)^T R[h][i] m23_h(t) )
// R (8x4x9x9) built once per launch by a prologue kernel.
// Main kernel: packed f32x2, 2 tokens/thread, 2 CTAs/SM (<=128 regs).
// ============================================================================

#define NQ      4
#define LAYERS  2
#define HEADS   8
#define EMBED   32
#define TOKENS  (32 * 4096)          // B*S = 131072
#define HALF_T  (TOKENS / 2)         // 65536 threads

__device__ float g_R[HEADS * 4 * 9 * 9];

typedef unsigned long long u64;

__device__ __forceinline__ u64 pack2(float a, float b) {
    u64 r; asm("mov.b64 %0, {%1, %2};" : "=l"(r) : "f"(a), "f"(b)); return r;
}
__device__ __forceinline__ void unpack2(u64 a, float& x, float& y) {
    asm("mov.b64 {%0, %1}, %2;" : "=f"(x), "=f"(y) : "l"(a));
}
__device__ __forceinline__ u64 fma2(u64 a, u64 b, u64 c) {
    u64 d; asm("fma.rn.f32x2 %0, %1, %2, %3;" : "=l"(d) : "l"(a), "l"(b), "l"(c)); return d;
}
__device__ __forceinline__ u64 mul2(u64 a, u64 b) {
    u64 d; asm("mul.rn.f32x2 %0, %1, %2;" : "=l"(d) : "l"(a), "l"(b)); return d;
}

// ---------------------------------------------------------------------------
// Prologue
// ---------------------------------------------------------------------------
// Composed permutation of the CNOT chain (0,1),(1,2),(2,3),(3,0).
// U_final[r][c] = U[perm(r)][c] with perm = g01∘g12∘g23∘g30 (g30 applied first).
__device__ __forceinline__ int cnot_perm(int r) {
    int s = r;
    if (s & 1) s ^= 8;   // g30: c=3(bit0), t=0(bit3)
    if (s & 2) s ^= 1;   // g23: c=2(bit1), t=3(bit0)
    if (s & 4) s ^= 2;   // g12: c=1(bit2), t=2(bit1)
    if (s & 8) s ^= 4;   // g01: c=0(bit3), t=1(bit2)
    return s;
}

__global__ void build_coeffs_kernel(const float* __restrict__ params) {
    __shared__ float Ur[16][16], Ui[16][16];
    __shared__ float A[16][16];

    const int h   = blockIdx.x >> 2;
    const int obs = blockIdx.x & 3;
    const int tid = threadIdx.x;
    const int r   = tid >> 4, c = tid & 15;

    Ur[r][c] = (r == c) ? 1.0f : 0.0f;
    Ui[r][c] = 0.0f;
    __syncthreads();

    for (int l = 0; l < LAYERS; l++) {
        for (int q = 0; q < NQ; q++) {
            const float* p = params + ((h * LAYERS + l) * NQ + q) * 3;
            float t0 = p[0], t1 = p[1], t2 = p[2];
            float c0 = cosf(0.5f * t0), s0 = sinf(0.5f * t0);
            float c1 = cosf(0.5f * t1), s1 = sinf(0.5f * t1);
            float cz = cosf(0.5f * t2), sz = sinf(0.5f * t2);
            // M = Ry(t1) * Rx(t0)
            float M00r =  c1 * c0, M00i =  s1 * s0;
            float M01r = -s1 * c0, M01i = -c1 * s0;
            float M10r =  s1 * c0, M10i = -c1 * s0;
            float M11r =  c1 * c0, M11i = -s1 * s0;
            // G = Rz(t2) * M
            float G00r = M00r * cz + M00i * sz, G00i = M00i * cz - M00r * sz;
            float G01r = M01r * cz + M01i * sz, G01i = M01i * cz - M01r * sz;
            float G10r = M10r * cz - M10i * sz, G10i = M10i * cz + M10r * sz;
            float G11r = M11r * cz - M11i * sz, G11i = M11i * cz + M11r * sz;

            if (tid < 128) {
                int pr = tid >> 4, col = tid & 15;
                int bp = 3 - q, msk = 1 << bp;
                int low = pr & (msk - 1);
                int r0 = ((pr >> bp) << (bp + 1)) | low;
                int r1 = r0 | msk;
                float ar = Ur[r0][col], ai = Ui[r0][col];
                float br = Ur[r1][col], bi = Ui[r1][col];
                Ur[r0][col] = G00r * ar - G00i * ai + G01r * br - G01i * bi;
                Ui[r0][col] = G00r * ai + G00i * ar + G01r * bi + G01i * br;
                Ur[r1][col] = G10r * ar - G10i * ai + G11r * br - G11i * bi;
                Ui[r1][col] = G10r * ai + G10i * ar + G11r * bi + G11i * br;
            }
            __syncthreads();
        }
        // one composed-permutation copy replaces the 4 CNOT passes
        {
            int src = cnot_perm(r);
            float vr = Ur[src][c], vi = Ui[src][c];
            __syncthreads();
            Ur[r][c] = vr; Ui[r][c] = vi;
            __syncthreads();
        }
    }

    // A[j][k] = sum_r D_obs[r] * (Ur[r][j]Ur[r][k] + Ui[r][j]Ui[r][k])
    {
        int j = r, k = c;
        int bp = 3 - obs;
        float s = 0.0f;
        #pragma unroll
        for (int rr = 0; rr < 16; rr++) {
            float sign = ((rr >> bp) & 1) ? -1.0f : 1.0f;
            s += sign * (Ur[rr][j] * Ur[rr][k] + Ui[rr][j] * Ui[rr][k]);
        }
        A[j][k] = s;
    }
    __syncthreads();

    // Sparse projection into the (1,cos,sin)^4 monomial basis.
    // For t=0: pairs (j,k)=(0,0),(1,1) w=+.5,+.5
    //     t=1: (0,0),(1,1) w=+.5,-.5
    //     t=2: (0,1),(1,0) w=+.5,+.5
    // => j bits = sel bits; k bits = sel ^ (bits where t_q==2);
    //    sign  = parity(sel & bits-where-t_q==1); magnitude = 0.5^4.
    if (tid < 81) {
        int t0 = tid / 27, t1 = (tid / 9) % 3, t2 = (tid / 3) % 3, t3 = tid % 3;
        int kflip = ((t0 == 2) ? 8 : 0) | ((t1 == 2) ? 4 : 0)
                  | ((t2 == 2) ? 2 : 0) | ((t3 == 2) ? 1 : 0);
        int mneg  = ((t0 == 1) ? 8 : 0) | ((t1 == 1) ? 4 : 0)
                  | ((t2 == 1) ? 2 : 0) | ((t3 == 1) ? 1 : 0);
        float s = 0.0f;
        #pragma unroll
        for (int sel = 0; sel < 16; sel++) {
            float v = A[sel][sel ^ kflip];
            s += (__popc(sel & mneg) & 1) ? -v : v;
        }
        g_R[((h * 4 + obs) * 9 + (t0 * 3 + t1)) * 9 + (t2 * 3 + t3)] = 0.0625f * s;
    }
}

// ---------------------------------------------------------------------------
// Main kernel: 2 tokens/thread, a-outer/i-inner (no m01 array => <=128 regs),
// coefficients duplicated in SMEM so LDS.128 yields packed f32x2 operands.
// ---------------------------------------------------------------------------
__global__ void __launch_bounds__(256, 2)
quantum_mha_kernel(const float* __restrict__ x,
                   const float* __restrict__ W,     // [32][32]
                   const float* __restrict__ bias,  // [32]
                   float* __restrict__ out) {
    // sR: [h][i][a][20] (9 coeffs duplicated -> 18 floats, pad to 20)
    __shared__ __align__(16) float sR[HEADS * 4 * 9 * 20];   // 23040 B
    __shared__ __align__(16) float sW[EMBED * 64];
    __shared__ __align__(16) float sb[64];

    const int tid = threadIdx.x;
    for (int idx = tid; idx < HEADS * 4 * 9 * 9; idx += 256) {
        int b   = idx % 9;
        int hia = idx / 9;
        float v = g_R[idx];
        sR[hia * 20 + 2 * b]     = v;
        sR[hia * 20 + 2 * b + 1] = v;
    }
    for (int idx = tid; idx < EMBED * 32; idx += 256) {
        int e = idx >> 5, k = idx & 31;
        float v = W[e * 32 + k];
        sW[e * 64 + 2 * k]     = v;
        sW[e * 64 + 2 * k + 1] = v;
    }
    if (tid < 32) { float v = bias[tid]; sb[2 * tid] = v; sb[2 * tid + 1] = v; }
    __syncthreads();

    const int gid = blockIdx.x * 256 + tid;       // 0..65535
    const int tA = gid;
    const int tB = gid + HALF_T;

    const float4* xA4 = reinterpret_cast<const float4*>(x + (size_t)tA * 32);
    const float4* xB4 = reinterpret_cast<const float4*>(x + (size_t)tB * 32);

    u64 oacc[EMBED];
    #pragma unroll
    for (int e = 0; e < EMBED; e++)
        oacc[e] = *reinterpret_cast<const u64*>(&sb[2 * e]);

    #pragma unroll 1
    for (int h = 0; h < HEADS; h++) {
        float4 aA = xA4[h];
        float4 aB = xB4[h];

        float cA0, sA0, cA1, sA1, cA2, sA2, cA3, sA3;
        float cB0, sB0, cB1, sB1, cB2, sB2, cB3, sB3;
        __sincosf(aA.x, &sA0, &cA0);  __sincosf(aA.y, &sA1, &cA1);
        __sincosf(aA.z, &sA2, &cA2);  __sincosf(aA.w, &sA3, &cA3);
        __sincosf(aB.x, &sB0, &cB0);  __sincosf(aB.y, &sB1, &cB1);
        __sincosf(aB.z, &sB2, &cB2);  __sincosf(aB.w, &sB3, &cB3);

        u64 C0 = pack2(cA0, cB0), S0 = pack2(sA0, sB0);
        u64 C1 = pack2(cA1, cB1), S1 = pack2(sA1, sB1);
        u64 C2 = pack2(cA2, cB2), S2 = pack2(sA2, sB2);
        u64 C3 = pack2(cA3, cB3), S3 = pack2(sA3, sB3);

        // column monomials (qubits 2,3); kept live all head
        u64 M1 = C3, M2 = S3, M3 = C2;
        u64 M4 = mul2(C2, C3), M5 = mul2(C2, S3);
        u64 M6 = S2, M7 = mul2(S2, C3), M8 = mul2(S2, S3);

        const float* base = sR + h * (4 * 9 * 20);
        u64 ev[4];

        #pragma unroll
        for (int a = 0; a < 9; a++) {
            // row monomial m01[a], computed inline (consumed immediately)
            u64 ma = 0;
            switch (a) {
                case 1: ma = C1; break;
                case 2: ma = S1; break;
                case 3: ma = C0; break;
                case 4: ma = mul2(C0, C1); break;
                case 5: ma = mul2(C0, S1); break;
                case 6: ma = S0; break;
                case 7: ma = mul2(S0, C1); break;
                case 8: ma = mul2(S0, S1); break;
                default: break;
            }
            #pragma unroll
            for (int i = 0; i < 4; i++) {
                const float* rb = base + i * (9 * 20) + a * 20;
                const ulonglong2* r2 = reinterpret_cast<const ulonglong2*>(rb);
                ulonglong2 q0 = r2[0], q1 = r2[1], q2 = r2[2], q3 = r2[3];
                u64 q8 = *reinterpret_cast<const u64*>(rb + 16);
                u64 t = q0.x;
                t = fma2(M1, q0.y, t);
                t = fma2(M2, q1.x, t);
                t = fma2(M3, q1.y, t);
                t = fma2(M4, q2.x, t);
                t = fma2(M5, q2.y, t);
                t = fma2(M6, q3.x, t);
                t = fma2(M7, q3.y, t);
                t = fma2(M8, q8,   t);
                if (a == 0) ev[i] = t;             // m01[0] == 1
                else        ev[i] = fma2(ma, t, ev[i]);
            }
        }

        // fold into outputs: oacc[e] += sum_i W[e][4h+i] * ev[i]
        #pragma unroll
        for (int e = 0; e < EMBED; e++) {
            const ulonglong2* w2 =
                reinterpret_cast<const ulonglong2*>(sW + e * 64 + h * 8);
            ulonglong2 wa = w2[0], wb = w2[1];
            u64 acc = oacc[e];
            acc = fma2(ev[0], wa.x, acc);
            acc = fma2(ev[1], wa.y, acc);
            acc = fma2(ev[2], wb.x, acc);
            acc = fma2(ev[3], wb.y, acc);
            oacc[e] = acc;
        }
    }

    float4* oA4 = reinterpret_cast<float4*>(out + (size_t)tA * 32);
    float4* oB4 = reinterpret_cast<float4*>(out + (size_t)tB * 32);
    #pragma unroll
    for (int g = 0; g < 8; g++) {
        float4 va, vb;
        unpack2(oacc[4 * g + 0], va.x, vb.x);
        unpack2(oacc[4 * g + 1], va.y, vb.y);
        unpack2(oacc[4 * g + 2], va.z, vb.z);
        unpack2(oacc[4 * g + 3], va.w, vb.w);
        oA4[g] = va;
        oB4[g] = vb;
    }
}

// ---------------------------------------------------------------------------
extern "C" void kernel_launch(void* const* d_in, const int* in_sizes, int n_in,
                              void* d_out, int out_size) {
    const float* x = nullptr;
    const float* params = nullptr;
    const float* W = nullptr;
    const float* bias = nullptr;
    for (int i = 0; i < n_in; i++) {
        int s = in_sizes[i];
        if      (s == TOKENS * EMBED)            x      = (const float*)d_in[i];
        else if (s == HEADS * LAYERS * NQ * 3)   params = (const float*)d_in[i];
        else if (s == EMBED * EMBED)             W      = (const float*)d_in[i];
        else if (s == EMBED)                     bias   = (const float*)d_in[i];
    }
    float* out = (float*)d_out;

    build_coeffs_kernel<<<HEADS * 4, 256>>>(params);
    quantum_mha_kernel<<<HALF_T / 256, 256>>>(x, W, bias, out);
}

// round 10
// speedup vs baseline: 2.3193x; 1.9747x over previous
#include <cuda_runtime.h>
#include <cstdint>

// ============================================================================
// MultiHeadAttentionQuantum — algebraic collapse:
//   out[t,e] = b[e] + sum_{h,i} W[e,4h+i] * ( m01_h(t)^T R[h][i] m23_h(t) )
// R (8x4x9x9) built once per launch by a prologue kernel.
// Main kernel: f32x2 packed over the OBSERVABLE axis (i0,i1)/(i2,i3) so each
// broadcast LDS.128 of interleaved coefficients feeds 4 fma2 (2 pairs x 2
// tokens). x staged in SMEM (coalesced). 2 tokens/thread, 3 CTAs/SM.
// ============================================================================

#define NQ      4
#define LAYERS  2
#define HEADS   8
#define EMBED   32
#define TOKENS  (32 * 4096)          // B*S = 131072
#define HALF_T  (TOKENS / 2)         // 65536 threads
#define TPB     128
#define XPITCH  36                   // floats per staged x row (bank-safe)

__device__ float g_R[HEADS * 4 * 9 * 9];

typedef unsigned long long u64;

__device__ __forceinline__ u64 pack2(float a, float b) {
    u64 r; asm("mov.b64 %0, {%1, %2};" : "=l"(r) : "f"(a), "f"(b)); return r;
}
__device__ __forceinline__ u64 dup2(float a) {
    u64 r; asm("mov.b64 %0, {%1, %1};" : "=l"(r) : "f"(a)); return r;
}
__device__ __forceinline__ void unpack2(u64 a, float& x, float& y) {
    asm("mov.b64 {%0, %1}, %2;" : "=f"(x), "=f"(y) : "l"(a));
}
__device__ __forceinline__ u64 fma2(u64 a, u64 b, u64 c) {
    u64 d; asm("fma.rn.f32x2 %0, %1, %2, %3;" : "=l"(d) : "l"(a), "l"(b), "l"(c)); return d;
}
__device__ __forceinline__ u64 mul2(u64 a, u64 b) {
    u64 d; asm("mul.rn.f32x2 %0, %1, %2;" : "=l"(d) : "l"(a), "l"(b)); return d;
}

// ---------------------------------------------------------------------------
// Prologue (unchanged from R6 — passes, ~fast)
// ---------------------------------------------------------------------------
__device__ __forceinline__ int cnot_perm(int r) {
    int s = r;
    if (s & 1) s ^= 8;
    if (s & 2) s ^= 1;
    if (s & 4) s ^= 2;
    if (s & 8) s ^= 4;
    return s;
}

__global__ void build_coeffs_kernel(const float* __restrict__ params) {
    __shared__ float Ur[16][16], Ui[16][16];
    __shared__ float A[16][16];

    const int h   = blockIdx.x >> 2;
    const int obs = blockIdx.x & 3;
    const int tid = threadIdx.x;
    const int r   = tid >> 4, c = tid & 15;

    Ur[r][c] = (r == c) ? 1.0f : 0.0f;
    Ui[r][c] = 0.0f;
    __syncthreads();

    for (int l = 0; l < LAYERS; l++) {
        for (int q = 0; q < NQ; q++) {
            const float* p = params + ((h * LAYERS + l) * NQ + q) * 3;
            float t0 = p[0], t1 = p[1], t2 = p[2];
            float c0 = cosf(0.5f * t0), s0 = sinf(0.5f * t0);
            float c1 = cosf(0.5f * t1), s1 = sinf(0.5f * t1);
            float cz = cosf(0.5f * t2), sz = sinf(0.5f * t2);
            float M00r =  c1 * c0, M00i =  s1 * s0;
            float M01r = -s1 * c0, M01i = -c1 * s0;
            float M10r =  s1 * c0, M10i = -c1 * s0;
            float M11r =  c1 * c0, M11i = -s1 * s0;
            float G00r = M00r * cz + M00i * sz, G00i = M00i * cz - M00r * sz;
            float G01r = M01r * cz + M01i * sz, G01i = M01i * cz - M01r * sz;
            float G10r = M10r * cz - M10i * sz, G10i = M10i * cz + M10r * sz;
            float G11r = M11r * cz - M11i * sz, G11i = M11i * cz + M11r * sz;

            if (tid < 128) {
                int pr = tid >> 4, col = tid & 15;
                int bp = 3 - q, msk = 1 << bp;
                int low = pr & (msk - 1);
                int r0 = ((pr >> bp) << (bp + 1)) | low;
                int r1 = r0 | msk;
                float ar = Ur[r0][col], ai = Ui[r0][col];
                float br = Ur[r1][col], bi = Ui[r1][col];
                Ur[r0][col] = G00r * ar - G00i * ai + G01r * br - G01i * bi;
                Ui[r0][col] = G00r * ai + G00i * ar + G01r * bi + G01i * br;
                Ur[r1][col] = G10r * ar - G10i * ai + G11r * br - G11i * bi;
                Ui[r1][col] = G10r * ai + G10i * ar + G11r * bi + G11i * br;
            }
            __syncthreads();
        }
        {
            int src = cnot_perm(r);
            float vr = Ur[src][c], vi = Ui[src][c];
            __syncthreads();
            Ur[r][c] = vr; Ui[r][c] = vi;
            __syncthreads();
        }
    }

    {
        int j = r, k = c;
        int bp = 3 - obs;
        float s = 0.0f;
        #pragma unroll
        for (int rr = 0; rr < 16; rr++) {
            float sign = ((rr >> bp) & 1) ? -1.0f : 1.0f;
            s += sign * (Ur[rr][j] * Ur[rr][k] + Ui[rr][j] * Ui[rr][k]);
        }
        A[j][k] = s;
    }
    __syncthreads();

    if (tid < 81) {
        int t0 = tid / 27, t1 = (tid / 9) % 3, t2 = (tid / 3) % 3, t3 = tid % 3;
        int kflip = ((t0 == 2) ? 8 : 0) | ((t1 == 2) ? 4 : 0)
                  | ((t2 == 2) ? 2 : 0) | ((t3 == 2) ? 1 : 0);
        int mneg  = ((t0 == 1) ? 8 : 0) | ((t1 == 1) ? 4 : 0)
                  | ((t2 == 1) ? 2 : 0) | ((t3 == 1) ? 1 : 0);
        float s = 0.0f;
        #pragma unroll
        for (int sel = 0; sel < 16; sel++) {
            float v = A[sel][sel ^ kflip];
            s += (__popc(sel & mneg) & 1) ? -v : v;
        }
        g_R[((h * 4 + obs) * 9 + (t0 * 3 + t1)) * 9 + (t2 * 3 + t3)] = 0.0625f * s;
    }
}

// ---------------------------------------------------------------------------
// Main kernel
// SMEM layout (dynamic, 51456 B):
//   xs  [256][36]  staged x rows (row 0..127 = token chunk A, 128..255 = B)
//   sR2 [h][a][b][i]  (i = 0..3 fastest)  -> LDS.128 gives pair01 | pair23
//   sW  [32][32]   W as-is (float4 per head = two pairs)
//   sb  [32]
// ---------------------------------------------------------------------------
__global__ void __launch_bounds__(TPB, 3)
quantum_mha_kernel(const float* __restrict__ x,
                   const float* __restrict__ W,
                   const float* __restrict__ bias,
                   float* __restrict__ out) {
    extern __shared__ float smem[];
    float* xs  = smem;                        // 256*36   = 9216
    float* sR2 = smem + 256 * XPITCH;         // 2592
    float* sW  = sR2 + HEADS * 4 * 9 * 9;     // 1024
    float* sb  = sW + EMBED * EMBED;          // 32

    const int tid = threadIdx.x;
    const int blk = blockIdx.x;

    // ---- fill coefficient SMEM (interleave i fastest) ----
    for (int idx = tid; idx < HEADS * 4 * 9 * 9; idx += TPB) {
        int i  = idx & 3;
        int ab = idx >> 2;
        int b  = ab % 9;
        int ha = ab / 9;
        int a  = ha % 9;
        int h  = ha / 9;
        sR2[idx] = g_R[((h * 4 + i) * 9 + a) * 9 + b];
    }
    for (int idx = tid; idx < EMBED * EMBED; idx += TPB) sW[idx] = W[idx];
    if (tid < 32) sb[tid] = bias[tid];

    // ---- stage x: 256 token rows (A chunk then B chunk), coalesced ----
    {
        const float4* xg = reinterpret_cast<const float4*>(x);
        #pragma unroll
        for (int k = 0; k < 16; k++) {
            int idx = tid + k * TPB;          // 0..2047
            int row = idx >> 3;               // 0..255
            int col = idx & 7;                // 0..7 (float4 index)
            long gtok = (row < TPB) ? (long)(blk * TPB + row)
                                    : (long)(blk * TPB + (row - TPB) + HALF_T);
            float4 v = xg[gtok * 8 + col];
            *reinterpret_cast<float4*>(xs + row * XPITCH + col * 4) = v;
        }
    }
    __syncthreads();

    // ev[h*4 + 0] = pair(i0,i1) tokA ; +1 = pair01 tokB ; +2 = pair23 tokA ; +3 = pair23 tokB
    u64 ev[HEADS * 4];

    #pragma unroll 1
    for (int h = 0; h < HEADS; h++) {
        float4 aA = *reinterpret_cast<const float4*>(xs + tid * XPITCH + h * 4);
        float4 aB = *reinterpret_cast<const float4*>(xs + (TPB + tid) * XPITCH + h * 4);

        float cA0, sA0, cA1, sA1, cA2, sA2, cA3, sA3;
        float cB0, sB0, cB1, sB1, cB2, sB2, cB3, sB3;
        __sincosf(aA.x, &sA0, &cA0);  __sincosf(aA.y, &sA1, &cA1);
        __sincosf(aA.z, &sA2, &cA2);  __sincosf(aA.w, &sA3, &cA3);
        __sincosf(aB.x, &sB0, &cB0);  __sincosf(aB.y, &sB1, &cB1);
        __sincosf(aB.z, &sB2, &cB2);  __sincosf(aB.w, &sB3, &cB3);

        // duplicated base monomials per token
        u64 dC0A = dup2(cA0), dS0A = dup2(sA0), dC1A = dup2(cA1), dS1A = dup2(sA1);
        u64 dC0B = dup2(cB0), dS0B = dup2(sB0), dC1B = dup2(cB1), dS1B = dup2(sB1);

        // m23 monomials (b index 1..8), duplicated, per token
        u64 mA[9], mB[9];
        {
            u64 dC2 = dup2(cA2), dS2 = dup2(sA2), dC3 = dup2(cA3), dS3 = dup2(sA3);
            mA[1] = dC3; mA[2] = dS3; mA[3] = dC2;
            mA[4] = mul2(dC2, dC3); mA[5] = mul2(dC2, dS3);
            mA[6] = dS2; mA[7] = mul2(dS2, dC3); mA[8] = mul2(dS2, dS3);
        }
        {
            u64 dC2 = dup2(cB2), dS2 = dup2(sB2), dC3 = dup2(cB3), dS3 = dup2(sB3);
            mB[1] = dC3; mB[2] = dS3; mB[3] = dC2;
            mB[4] = mul2(dC2, dC3); mB[5] = mul2(dC2, dS3);
            mB[6] = dS2; mB[7] = mul2(dS2, dC3); mB[8] = mul2(dS2, dS3);
        }

        const ulonglong2* rbase =
            reinterpret_cast<const ulonglong2*>(sR2 + (h * 9) * 9 * 4);

        #pragma unroll
        for (int a = 0; a < 9; a++) {
            // row monomial m01[a] per token, built inline
            u64 maA = 0, maB = 0;
            switch (a) {
                case 1: maA = dC1A; maB = dC1B; break;
                case 2: maA = dS1A; maB = dS1B; break;
                case 3: maA = dC0A; maB = dC0B; break;
                case 4: maA = mul2(dC0A, dC1A); maB = mul2(dC0B, dC1B); break;
                case 5: maA = mul2(dC0A, dS1A); maB = mul2(dC0B, dS1B); break;
                case 6: maA = dS0A; maB = dS0B; break;
                case 7: maA = mul2(dS0A, dC1A); maB = mul2(dS0B, dC1B); break;
                case 8: maA = mul2(dS0A, dS1A); maB = mul2(dS0B, dS1B); break;
                default: break;
            }

            const ulonglong2* rb = rbase + a * 9;
            u64 i01A, i01B, i23A, i23B;
            {
                ulonglong2 q = rb[0];          // b = 0 (m23[0] == 1)
                i01A = q.x; i01B = q.x; i23A = q.y; i23B = q.y;
            }
            #pragma unroll
            for (int b = 1; b < 9; b++) {
                ulonglong2 q = rb[b];          // one LDS.128: pair01 | pair23
                i01A = fma2(mA[b], q.x, i01A);
                i01B = fma2(mB[b], q.x, i01B);
                i23A = fma2(mA[b], q.y, i23A);
                i23B = fma2(mB[b], q.y, i23B);
            }
            if (a == 0) {
                ev[h * 4 + 0] = i01A; ev[h * 4 + 1] = i01B;
                ev[h * 4 + 2] = i23A; ev[h * 4 + 3] = i23B;
            } else {
                ev[h * 4 + 0] = fma2(maA, i01A, ev[h * 4 + 0]);
                ev[h * 4 + 1] = fma2(maB, i01B, ev[h * 4 + 1]);
                ev[h * 4 + 2] = fma2(maA, i23A, ev[h * 4 + 2]);
                ev[h * 4 + 3] = fma2(maB, i23B, ev[h * 4 + 3]);
            }
        }
    }

    // ---- W fold: per e, acc pair = sum_h ev01*w01 + ev23*w23; horizontal once ----
    const int gid = blk * TPB + tid;
    float4* oA4 = reinterpret_cast<float4*>(out + (size_t)gid * 32);
    float4* oB4 = reinterpret_cast<float4*>(out + ((size_t)gid + HALF_T) * 32);

    #pragma unroll
    for (int eg = 0; eg < 8; eg++) {
        float4 oA, oB;
        float4 bq = *reinterpret_cast<const float4*>(sb + eg * 4);
        #pragma unroll
        for (int j = 0; j < 4; j++) {
            int e = eg * 4 + j;
            const ulonglong2* wrow =
                reinterpret_cast<const ulonglong2*>(sW + e * 32);
            u64 accA, accB;
            {
                ulonglong2 w = wrow[0];
                accA = mul2(ev[0], w.x); accA = fma2(ev[2], w.y, accA);
                accB = mul2(ev[1], w.x); accB = fma2(ev[3], w.y, accB);
            }
            #pragma unroll
            for (int hh = 1; hh < 8; hh++) {
                ulonglong2 w = wrow[hh];
                accA = fma2(ev[hh * 4 + 0], w.x, accA);
                accA = fma2(ev[hh * 4 + 2], w.y, accA);
                accB = fma2(ev[hh * 4 + 1], w.x, accB);
                accB = fma2(ev[hh * 4 + 3], w.y, accB);
            }
            float aLo, aHi, bLo, bHi;
            unpack2(accA, aLo, aHi);
            unpack2(accB, bLo, bHi);
            float be = (&bq.x)[j];
            (&oA.x)[j] = aLo + aHi + be;
            (&oB.x)[j] = bLo + bHi + be;
        }
        oA4[eg] = oA;
        oB4[eg] = oB;
    }
}

// ---------------------------------------------------------------------------
extern "C" void kernel_launch(void* const* d_in, const int* in_sizes, int n_in,
                              void* d_out, int out_size) {
    const float* x = nullptr;
    const float* params = nullptr;
    const float* W = nullptr;
    const float* bias = nullptr;
    for (int i = 0; i < n_in; i++) {
        int s = in_sizes[i];
        if      (s == TOKENS * EMBED)            x      = (const float*)d_in[i];
        else if (s == HEADS * LAYERS * NQ * 3)   params = (const float*)d_in[i];
        else if (s == EMBED * EMBED)             W      = (const float*)d_in[i];
        else if (s == EMBED)                     bias   = (const float*)d_in[i];
    }
    float* out = (float*)d_out;

    const int smem_bytes = (256 * XPITCH + HEADS * 4 * 9 * 9 + EMBED * EMBED + 32)
                           * (int)sizeof(float);   // 51456
    cudaFuncSetAttribute(quantum_mha_kernel,
                         cudaFuncAttributeMaxDynamicSharedMemorySize, smem_bytes);

    build_coeffs_kernel<<<HEADS * 4, 256>>>(params);
    quantum_mha_kernel<<<HALF_T / TPB, TPB, smem_bytes>>>(x, W, bias, out);
}